// round 5
// baseline (speedup 1.0000x reference)
#include <cuda_runtime.h>

// Shapes (fixed):
//   p1: [6,256,256] f32   bank
//   p2: [131072,256] f32  table
//   p3: [6,1] i32         row ids into p2
//   p4: [1,256] i32       gather columns
//   p5: [6,1] i32         slot (c index) per batch
//   p6: [1,256] i32       scatter columns
//   p7: [6,256,256] f32   EMA state
//   p8: [12,6,256] f32    query features
// out1: [12,6,256] f32, out2: [6,256,256] f32 (concatenated in d_out)

#define B 6
#define S 256
#define D 256
#define A 12
#define CS 16            // c-splits
#define CLEN (S / CS)    // 16 c per block
#define DT 64            // d per tile
#define ABD (A * B * D)  // 18432

// Partial out1 sums, one slice per c-split. 16*18432*4B = 1.15 MB.
__device__ float g_partial[CS * ABD];

// Fused kernel: grid = (D/64, B, CS) = (4, 6, 16) = 384 blocks, 256 threads.
// Thread map: tx = t&15 (float4 d lane -> 64 d), ty = t>>4 (c lane, 1 c each).
// Per block tile: add[c0:c0+16, d0:d0+64] for one b.
//   val = (c==slot ? scattered row : p1) + 0.975*p7     (2 float4 LDG/thread)
//   -> smem tile s[c][d]
//   out2[b,d,c] = s[c][d]            (transpose drain)
//   partial[cs,a,b,d] = sum_c p8[a,b,c]*s[c][d]   (micro-GEMM from smem)
__global__ __launch_bounds__(256)
void fused_kernel(const float* __restrict__ p1,
                  const float* __restrict__ p2,
                  const int* __restrict__ p3,
                  const int* __restrict__ p4,
                  const int* __restrict__ p5,
                  const int* __restrict__ p6,
                  const float* __restrict__ p7,
                  const float* __restrict__ p8,
                  float* __restrict__ out2) {
    __shared__ float p8s[A * CLEN];       // 768 B
    __shared__ float4 g4[DT / 4];         // scattered-row slice, 64 d
    __shared__ float s[CLEN][DT + 4];     // 16 x 68 floats (v4-aligned rows)

    const int d0 = blockIdx.x * DT;
    const int b  = blockIdx.y;
    const int cs = blockIdx.z;
    const int c0 = cs * CLEN;
    const int t  = threadIdx.x;
    const int tx = t & 15;
    const int ty = t >> 4;
    const int slot = p5[b];

    // Stage p8 slice: p8s[a*16 + cl] = p8[a,b,c0+cl]
    if (t < A * CLEN) {
        int a = t >> 4, cl = t & 15;
        p8s[t] = p8[(a * B + b) * 256 + c0 + cl];
    }
    // Scattered row base: p1[b, slot, d0:d0+64]
    if (t < DT / 4)
        g4[t] = ((const float4*)(p1 + (b * S + slot) * D + d0))[t];
    __syncthreads();
    // Patch: row[p6[j]] = p2[p3[b], p4[j]] where it lands in this d tile.
    {
        int col = p6[t];
        if (col >= d0 && col < d0 + DT)
            ((float*)g4)[col - d0] = p2[(long long)p3[b] * D + p4[t]];
    }
    __syncthreads();

    const float* p1b = p1 + b * (S * D);
    const float* p7b = p7 + b * (S * D);
    float* out2b = out2 + b * (S * D);

    // Main loads: one c per thread, float4 along d (coalesced 256B per half-warp).
    const int c = c0 + ty;
    float4 v1 = ((const float4*)(p1b + c * D + d0))[tx];
    float4 v7 = ((const float4*)(p7b + c * D + d0))[tx];
    float4 base = (c == slot) ? g4[tx] : v1;
    float4 val;
    val.x = fmaf(0.975f, v7.x, base.x);
    val.y = fmaf(0.975f, v7.y, base.y);
    val.z = fmaf(0.975f, v7.z, base.z);
    val.w = fmaf(0.975f, v7.w, base.w);
    ((float4*)&s[ty][0])[tx] = val;
    __syncthreads();

    // Drain out2: out2[b, d0+dl, c0+cl], consecutive threads -> consecutive c.
    {
        int cl = t & 15;
        int dl0 = t >> 4;
        #pragma unroll
        for (int p = 0; p < 4; p++) {
            int dl = dl0 + p * 16;
            out2b[(d0 + dl) * D + c0 + cl] = s[cl][dl];
        }
    }

    // Micro-GEMM: 768 outputs (a,dd); 3 per thread; fixed-order 16-c sum.
    #pragma unroll
    for (int k = 0; k < 3; k++) {
        int o  = t + 256 * k;
        int a  = o >> 6;
        int dd = o & 63;
        float sum = 0.f;
        #pragma unroll
        for (int cl = 0; cl < CLEN; cl++)
            sum = fmaf(p8s[a * CLEN + cl], s[cl][dd], sum);
        g_partial[cs * ABD + (a * B + b) * D + d0 + dd] = sum;
    }
}

// Sum the CS=16 partial slices into out1 with float4 loads (independent, unrolled).
__global__ __launch_bounds__(256)
void reduce_kernel(float* __restrict__ out1) {
    int v = blockIdx.x * 256 + threadIdx.x;      // vec4 index, ABD/4 = 4608
    if (v < ABD / 4) {
        const float4* part = (const float4*)g_partial;
        float4 sum = part[v];
        #pragma unroll
        for (int cs = 1; cs < CS; cs++) {
            float4 p = part[cs * (ABD / 4) + v];
            sum.x += p.x; sum.y += p.y; sum.z += p.z; sum.w += p.w;
        }
        ((float4*)out1)[v] = sum;
    }
}

extern "C" void kernel_launch(void* const* d_in, const int* in_sizes, int n_in,
                              void* d_out, int out_size) {
    const float* p1 = (const float*)d_in[0];
    const float* p2 = (const float*)d_in[1];
    const int*   p3 = (const int*)d_in[2];
    const int*   p4 = (const int*)d_in[3];
    const int*   p5 = (const int*)d_in[4];
    const int*   p6 = (const int*)d_in[5];
    const float* p7 = (const float*)d_in[6];
    const float* p8 = (const float*)d_in[7];

    float* out1 = (float*)d_out;                 // [12,6,256]
    float* out2 = out1 + ABD;                    // [6,256,256]

    dim3 grid(D / DT, B, CS);
    fused_kernel<<<grid, 256>>>(p1, p2, p3, p4, p5, p6, p7, p8, out2);
    reduce_kernel<<<(ABD / 4 + 255) / 256, 256>>>(out1);
}